// round 17
// baseline (speedup 1.0000x reference)
#include <cuda_runtime.h>
#include <cuda_bf16.h>
#include <math.h>
#include <float.h>
#include <stdint.h>

// Problem constants (match reference)
#define NN 100000
#define NE 1600000
#define NF 128
#define NL 7
#define SLOPE 0.02f
#define CAP 64            // bucket capacity per node; P(deg>64)~1e-18 for Poisson(16)
#define NT 1563           // ceil(100000 / 64) M-tiles

// ---------------- device scratch (static, no allocation) ----------------
// g_counts zero-init at load; aggout re-zeroes it at the end of every call.
__device__ int g_counts[NN];
__device__ int g_col[NN * CAP];
__device__ __align__(16) float g_h0[NN * NF];
__device__ __align__(16) float g_h1[NN * NF];
__device__ __align__(16) uint32_t g_aggP[NN * NF];   // packed (bf16hi<<16)|bf16lo
// pre-split weights: hi/lo bf16, layout [l][n][k]
__device__ __align__(16) uint16_t g_WlHi[NL * NF * NF];
__device__ __align__(16) uint16_t g_WlLo[NL * NF * NF];
__device__ __align__(16) uint16_t g_WrHi[NL * NF * NF];
__device__ __align__(16) uint16_t g_WrLo[NL * NF * NF];

// ---------------- bucket CSR fill + weight pre-split (single launch) ----------------
__global__ void fill_kernel(const int* __restrict__ src, const int* __restrict__ dst,
                            const float* __restrict__ Wl, const float* __restrict__ Wr) {
    int e = blockIdx.x * blockDim.x + threadIdx.x;
    if (e < NE) {
        int d = dst[e];
        int off = atomicAdd(&g_counts[d], 1);
        g_col[d * CAP + off] = src[e];
    }
    if (e < NL * NF * NF) {
        float a = Wl[e];
        __nv_bfloat16 h = __float2bfloat16(a);
        g_WlHi[e] = __bfloat16_as_ushort(h);
        g_WlLo[e] = __bfloat16_as_ushort(__float2bfloat16(a - __bfloat162float(h)));
        float b = Wr[e];
        __nv_bfloat16 hb = __float2bfloat16(b);
        g_WrHi[e] = __bfloat16_as_ushort(hb);
        g_WrLo[e] = __bfloat16_as_ushort(__float2bfloat16(b - __bfloat162float(hb)));
    }
}

// ---------------- helpers ----------------
__device__ __forceinline__ float4 fmax4(float4 a, float4 b) {
    a.x = fmaxf(a.x, b.x); a.y = fmaxf(a.y, b.y);
    a.z = fmaxf(a.z, b.z); a.w = fmaxf(a.w, b.w);
    return a;
}

__device__ __forceinline__ uint32_t smem_u32(const void* p) {
    uint32_t a;
    asm("{ .reg .u64 t; cvta.to.shared.u64 t, %1; cvt.u32.u64 %0, t; }" : "=r"(a) : "l"(p));
    return a;
}

__device__ __forceinline__ void ldm4(uint32_t* r, uint32_t addr) {
    asm volatile("ldmatrix.sync.aligned.m8n8.x4.shared.b16 {%0,%1,%2,%3}, [%4];"
                 : "=r"(r[0]), "=r"(r[1]), "=r"(r[2]), "=r"(r[3]) : "r"(addr));
}

__device__ __forceinline__ void mma_bf16(float* d, const uint32_t* a, uint32_t b0, uint32_t b1) {
    asm volatile(
        "mma.sync.aligned.m16n8k16.row.col.f32.bf16.bf16.f32 "
        "{%0,%1,%2,%3}, {%4,%5,%6,%7}, {%8,%9}, {%0,%1,%2,%3};"
        : "+f"(d[0]), "+f"(d[1]), "+f"(d[2]), "+f"(d[3])
        : "r"(a[0]), "r"(a[1]), "r"(a[2]), "r"(a[3]), "r"(b0), "r"(b1));
}

__device__ __forceinline__ void cp16(uint32_t d, const void* s) {
    asm volatile("cp.async.cg.shared.global [%0], [%1], 16;" :: "r"(d), "l"(s));
}

// pack fp32 -> (bf16hi<<16)|bf16lo
__device__ __forceinline__ uint32_t pack1(float v) {
    __nv_bfloat16 h = __float2bfloat16(v);
    __nv_bfloat16 l = __float2bfloat16(v - __bfloat162float(h));
    return ((uint32_t)__bfloat16_as_ushort(h) << 16) | __bfloat16_as_ushort(l);
}

// ---------------- max aggregation: fp32 gather from buckets, packed output ----------------
__global__ __launch_bounds__(256) void agg_kernel(const float* __restrict__ h,
                                                  uint32_t* __restrict__ aggP) {
    int warp = (blockIdx.x * blockDim.x + threadIdx.x) >> 5;
    int lane = threadIdx.x & 31;
    if (warp >= NN) return;
    int cnt = g_counts[warp];
    const int* col = &g_col[warp * CAP];
    const float4* h4 = (const float4*)h;
    float4 m = make_float4(-FLT_MAX, -FLT_MAX, -FLT_MAX, -FLT_MAX);
    int e = 0;
    for (; e + 8 <= cnt; e += 8) {
        float4 v0 = h4[col[e]     * 32 + lane];
        float4 v1 = h4[col[e + 1] * 32 + lane];
        float4 v2 = h4[col[e + 2] * 32 + lane];
        float4 v3 = h4[col[e + 3] * 32 + lane];
        float4 v4 = h4[col[e + 4] * 32 + lane];
        float4 v5 = h4[col[e + 5] * 32 + lane];
        float4 v6 = h4[col[e + 6] * 32 + lane];
        float4 v7 = h4[col[e + 7] * 32 + lane];
        m = fmax4(m, fmax4(fmax4(fmax4(v0, v1), fmax4(v2, v3)),
                           fmax4(fmax4(v4, v5), fmax4(v6, v7))));
    }
    for (; e < cnt; e++) m = fmax4(m, h4[col[e] * 32 + lane]);
    if (cnt == 0) m = make_float4(0.f, 0.f, 0.f, 0.f);
    uint4 pk = make_uint4(pack1(m.x), pack1(m.y), pack1(m.z), pack1(m.w));
    ((uint4*)aggP)[warp * 32 + lane] = pk;
}

// ========== persistent bf16x3 dual GEMM: W resident, M=64 tiles, reg-pipelined A ==========
#define A_STRIDE 272
#define W_PLANE  34816                 // 128 n-rows * 272
#define A_PLANE  17408                 // 64 rows * 272
#define A_BASE   (4 * W_PLANE)         // 139264
#define SM_TOT   (A_BASE + 4 * A_PLANE)   // 208896

// load registers for tile row0 (64 rows): 8 packed uint4 + 8 fp32 float4 per thread
__device__ __forceinline__ void ldA(const uint4* __restrict__ aggP4,
                                    const float4* __restrict__ h4,
                                    int row0, int tid, uint4 pk[8], float4 hv[8]) {
#pragma unroll
    for (int i = 0; i < 8; i++) {
        int idx = tid + i * 256;        // 0..2047
        int row = idx >> 5;             // 0..63
        int q   = idx & 31;
        int gm  = row0 + row;
        if (gm < NN) {
            pk[i] = aggP4[(size_t)gm * 32 + q];
            hv[i] = h4[(size_t)gm * 32 + q];
        } else {
            pk[i] = make_uint4(0, 0, 0, 0);
            hv[i] = make_float4(0.f, 0.f, 0.f, 0.f);
        }
    }
}

// convert + store the loaded tile into the A buffer
__device__ __forceinline__ void stA(char* smem, int tid,
                                    const uint4 pk[8], const float4 hv[8]) {
#pragma unroll
    for (int i = 0; i < 8; i++) {
        int idx = tid + i * 256;
        int row = idx >> 5;
        int q   = idx & 31;
        uint32_t off = (uint32_t)(row * A_STRIDE + q * 8);
        // packed agg -> planes 0,1
        uint4 p = pk[i];
        *(uint2*)(smem + A_BASE + off) =
            make_uint2(__byte_perm(p.x, p.y, 0x7632), __byte_perm(p.z, p.w, 0x7632));
        *(uint2*)(smem + A_BASE + A_PLANE + off) =
            make_uint2(__byte_perm(p.x, p.y, 0x5410), __byte_perm(p.z, p.w, 0x5410));
        // fp32 h -> planes 2,3
        float4 v = hv[i];
        __nv_bfloat16 hx = __float2bfloat16(v.x);
        __nv_bfloat16 hy = __float2bfloat16(v.y);
        __nv_bfloat16 hz = __float2bfloat16(v.z);
        __nv_bfloat16 hw = __float2bfloat16(v.w);
        uint32_t hi01 = ((uint32_t)__bfloat16_as_ushort(hy) << 16) | __bfloat16_as_ushort(hx);
        uint32_t hi23 = ((uint32_t)__bfloat16_as_ushort(hw) << 16) | __bfloat16_as_ushort(hz);
        __nv_bfloat16 lx = __float2bfloat16(v.x - __bfloat162float(hx));
        __nv_bfloat16 ly = __float2bfloat16(v.y - __bfloat162float(hy));
        __nv_bfloat16 lz = __float2bfloat16(v.z - __bfloat162float(hz));
        __nv_bfloat16 lw = __float2bfloat16(v.w - __bfloat162float(hw));
        uint32_t lo01 = ((uint32_t)__bfloat16_as_ushort(ly) << 16) | __bfloat16_as_ushort(lx);
        uint32_t lo23 = ((uint32_t)__bfloat16_as_ushort(lw) << 16) | __bfloat16_as_ushort(lz);
        *(uint2*)(smem + A_BASE + 2 * A_PLANE + off) = make_uint2(hi01, hi23);
        *(uint2*)(smem + A_BASE + 3 * A_PLANE + off) = make_uint2(lo01, lo23);
    }
}

// one half: acc += A(16r x 128k) @ W^T(64 cols); interleaved emission over 8 chains
__device__ __forceinline__ void mma_half64(float acc[8][4],
                                           uint32_t aHiB, uint32_t aLoB,
                                           uint32_t bHiB, uint32_t bLoB) {
#pragma unroll
    for (int ks = 0; ks < 8; ks++) {
        uint32_t ko = ks * 32;
        uint32_t ah[4], al[4];
        ldm4(ah, aHiB + ko);
        ldm4(al, aLoB + ko);
#pragma unroll
        for (int p = 0; p < 4; p++) {
            uint32_t bh[4], blx[4];
            uint32_t po = (uint32_t)(p * 16 * A_STRIDE) + ko;
            ldm4(bh,  bHiB + po);
            ldm4(blx, bLoB + po);
            float* d0 = acc[2 * p];
            float* d1 = acc[2 * p + 1];
            mma_bf16(d0, ah, bh[0],  bh[1]);
            mma_bf16(d1, ah, bh[2],  bh[3]);
            mma_bf16(d0, ah, blx[0], blx[1]);
            mma_bf16(d1, ah, blx[2], blx[3]);
            mma_bf16(d0, al, bh[0],  bh[1]);
            mma_bf16(d1, al, bh[2],  bh[3]);
        }
    }
}

__global__ __launch_bounds__(256, 1) void gemm_kernel(
    const uint32_t* __restrict__ aggP, const float* __restrict__ h,
    const uint16_t* __restrict__ WlHi, const uint16_t* __restrict__ WlLo,
    const uint16_t* __restrict__ WrHi, const uint16_t* __restrict__ WrLo,
    const float* __restrict__ bias, float* __restrict__ C)
{
    extern __shared__ char smem[];
    uint32_t su = smem_u32(smem);
    int tid = threadIdx.x;
    int lane = tid & 31;
    int wid = tid >> 5;
    int wm = wid & 3;        // 4 M-groups x 16 rows
    int wn = wid >> 2;       // 2 N-groups x 64 cols

    // ---- prologue: load all 4 W planes (resident for the whole kernel) ----
    {
        const uint16_t* srcs[4] = {WlHi, WlLo, WrHi, WrLo};
#pragma unroll
        for (int i = 0; i < 32; i++) {
            int idx = tid + i * 256;        // 0..8191
            int plane = idx >> 11;
            int rem = idx & 2047;
            int nl = rem >> 4;              // 0..127
            int q  = rem & 15;
            uint32_t dst = su + plane * W_PLANE + nl * A_STRIDE + q * 16;
            cp16(dst, srcs[plane] + (size_t)nl * NF + q * 8);
        }
        asm volatile("cp.async.commit_group;" ::: "memory");
    }

    // per-lane ldmatrix bases
    int lr = lane & 7, g = lane >> 3;
    uint32_t aOff = (uint32_t)((wm * 16 + lr + (g & 1) * 8) * A_STRIDE + (g >> 1) * 16);
    uint32_t bOff = (uint32_t)((wn * 64 + lr + (g >> 1) * 8) * A_STRIDE + (g & 1) * 16);
    uint32_t wlHiB = su + 0 * W_PLANE + bOff, wlLoB = su + 1 * W_PLANE + bOff;
    uint32_t wrHiB = su + 2 * W_PLANE + bOff, wrLoB = su + 3 * W_PLANE + bOff;
    uint32_t aggHiB = su + A_BASE + aOff;
    uint32_t aggLoB = su + A_BASE + A_PLANE + aOff;
    uint32_t hHiB   = su + A_BASE + 2 * A_PLANE + aOff;
    uint32_t hLoB   = su + A_BASE + 3 * A_PLANE + aOff;

    // bias registers (columns fixed per warp across tiles)
    float bs0[8], bs1[8];
#pragma unroll
    for (int c = 0; c < 8; c++) {
        int col = wn * 64 + (c >> 1) * 16 + (c & 1) * 8 + 2 * (lane & 3);
        bs0[c] = bias[col];
        bs1[c] = bias[col + 1];
    }

    const uint4*  aggP4 = (const uint4*)aggP;
    const float4* h4    = (const float4*)h;

    int t = blockIdx.x;
    int G = gridDim.x;

    // stage tile t
    uint4 pk[8]; float4 hv[8];
    ldA(aggP4, h4, t * 64, tid, pk, hv);
    asm volatile("cp.async.wait_group 0;" ::: "memory");
    stA(smem, tid, pk, hv);
    __syncthreads();

    for (; t < NT; t += G) {
        int tn = t + G;
        if (tn < NT) ldA(aggP4, h4, tn * 64, tid, pk, hv);   // loads in flight under mma

        float acc[8][4];
#pragma unroll
        for (int i = 0; i < 8; i++)
#pragma unroll
            for (int q = 0; q < 4; q++) acc[i][q] = 0.f;

        mma_half64(acc, aggHiB, aggLoB, wlHiB, wlLoB);       // agg @ Wl
        mma_half64(acc, hHiB,   hLoB,   wrHiB, wrLoB);       // h @ Wr

        // epilogue: bias + leaky, fp32 stores (guard last tile)
        int r0 = t * 64 + wm * 16 + (lane >> 2);
#pragma unroll
        for (int c = 0; c < 8; c++) {
            int col = wn * 64 + (c >> 1) * 16 + (c & 1) * 8 + 2 * (lane & 3);
            float v0 = acc[c][0] + bs0[c];
            float v1 = acc[c][1] + bs1[c];
            float v2 = acc[c][2] + bs0[c];
            float v3 = acc[c][3] + bs1[c];
            v0 = (v0 >= 0.f) ? v0 : SLOPE * v0;
            v1 = (v1 >= 0.f) ? v1 : SLOPE * v1;
            v2 = (v2 >= 0.f) ? v2 : SLOPE * v2;
            v3 = (v3 >= 0.f) ? v3 : SLOPE * v3;
            if (r0 < NN)     *((float2*)&C[(size_t)r0 * NF + col])       = make_float2(v0, v1);
            if (r0 + 8 < NN) *((float2*)&C[(size_t)(r0 + 8) * NF + col]) = make_float2(v2, v3);
        }

        __syncthreads();                     // all warps done reading A
        if (tn < NT) {
            stA(smem, tid, pk, hv);
            __syncthreads();
        }
    }
}

// ---------------- fused final layer: gather + output; zeroes counts for next call ----------------
__global__ __launch_bounds__(256) void aggout_kernel(
    const float* __restrict__ h,
    const float* __restrict__ Wl, const float* __restrict__ bl,
    const float* __restrict__ Wr, float* __restrict__ out)
{
    int warp = (blockIdx.x * blockDim.x + threadIdx.x) >> 5;
    int lane = threadIdx.x & 31;
    if (warp >= NN) return;
    int cnt = g_counts[warp];
    const int* col = &g_col[warp * CAP];
    const float4* h4 = (const float4*)h;
    float4 m = make_float4(-FLT_MAX, -FLT_MAX, -FLT_MAX, -FLT_MAX);
    int e = 0;
    for (; e + 8 <= cnt; e += 8) {
        float4 v0 = h4[col[e]     * 32 + lane];
        float4 v1 = h4[col[e + 1] * 32 + lane];
        float4 v2 = h4[col[e + 2] * 32 + lane];
        float4 v3 = h4[col[e + 3] * 32 + lane];
        float4 v4 = h4[col[e + 4] * 32 + lane];
        float4 v5 = h4[col[e + 5] * 32 + lane];
        float4 v6 = h4[col[e + 6] * 32 + lane];
        float4 v7 = h4[col[e + 7] * 32 + lane];
        m = fmax4(m, fmax4(fmax4(fmax4(v0, v1), fmax4(v2, v3)),
                           fmax4(fmax4(v4, v5), fmax4(v6, v7))));
    }
    for (; e < cnt; e++) m = fmax4(m, h4[col[e] * 32 + lane]);
    if (cnt == 0) m = make_float4(0.f, 0.f, 0.f, 0.f);

    float4 hv = h4[warp * 32 + lane];
#pragma unroll
    for (int o = 0; o < 3; o++) {
        float4 wl = ((const float4*)Wl)[o * 32 + lane];
        float4 wr = ((const float4*)Wr)[o * 32 + lane];
        float s = m.x * wl.x + m.y * wl.y + m.z * wl.z + m.w * wl.w
                + hv.x * wr.x + hv.y * wr.y + hv.z * wr.z + hv.w * wr.w;
#pragma unroll
        for (int off = 16; off; off >>= 1)
            s += __shfl_xor_sync(0xffffffff, s, off);
        if (lane == 0) out[warp * 3 + o] = tanhf(s + bl[o]) * 0.5f;
    }
    if (lane == 0) g_counts[warp] = 0;
}

// ---------------- host launcher ----------------
extern "C" void kernel_launch(void* const* d_in, const int* in_sizes, int n_in,
                              void* d_out, int out_size)
{
    const float* x      = (const float*)d_in[0];
    const int*   ei     = (const int*)d_in[1];
    const float* Wl     = (const float*)d_in[2];
    const float* bl     = (const float*)d_in[3];
    const float* Wr     = (const float*)d_in[4];
    const float* Wl_out = (const float*)d_in[5];
    const float* bl_out = (const float*)d_in[6];
    const float* Wr_out = (const float*)d_in[7];
    float* out = (float*)d_out;

    const int* src = ei;
    const int* dst = ei + NE;

    void *pH0, *pH1, *pAggP, *pWlHi, *pWlLo, *pWrHi, *pWrLo;
    cudaGetSymbolAddress(&pH0, g_h0);
    cudaGetSymbolAddress(&pH1, g_h1);
    cudaGetSymbolAddress(&pAggP, g_aggP);
    cudaGetSymbolAddress(&pWlHi, g_WlHi);
    cudaGetSymbolAddress(&pWlLo, g_WlLo);
    cudaGetSymbolAddress(&pWrHi, g_WrHi);
    cudaGetSymbolAddress(&pWrLo, g_WrLo);
    float* h0  = (float*)pH0;
    float* h1  = (float*)pH1;
    uint32_t* aggP = (uint32_t*)pAggP;
    uint16_t* wlHi = (uint16_t*)pWlHi;
    uint16_t* wlLo = (uint16_t*)pWlLo;
    uint16_t* wrHi = (uint16_t*)pWrHi;
    uint16_t* wrLo = (uint16_t*)pWrLo;

    static int s_sm = 0;
    if (s_sm == 0) {
        cudaDeviceGetAttribute(&s_sm, cudaDevAttrMultiProcessorCount, 0);
        if (s_sm <= 0) s_sm = 148;
        cudaFuncSetAttribute(gemm_kernel, cudaFuncAttributeMaxDynamicSharedMemorySize, SM_TOT);
    }

    // bucket CSR fill + weight pre-split (counts zeroed by previous call's aggout)
    fill_kernel<<<(NE + 255) / 256, 256>>>(src, dst, Wl, Wr);

    const int AGG_BLOCKS = (NN + 7) / 8;
    int GEMM_BLOCKS = s_sm;
    if (GEMM_BLOCKS > NT) GEMM_BLOCKS = NT;

    const float* cur = x;
    for (int i = 0; i < NL; i++) {
        agg_kernel<<<AGG_BLOCKS, 256>>>(cur, aggP);
        float* nxt = (i & 1) ? h1 : h0;
        gemm_kernel<<<GEMM_BLOCKS, 256, SM_TOT>>>(
            aggP, cur,
            wlHi + (size_t)i * NF * NF, wlLo + (size_t)i * NF * NF,
            wrHi + (size_t)i * NF * NF, wrLo + (size_t)i * NF * NF,
            bl + i * NF, nxt);
        cur = nxt;
    }

    // fused final aggregation + output conv (+ counts reset)
    aggout_kernel<<<AGG_BLOCKS, 256>>>(cur, Wl_out, bl_out, Wr_out, out);
}